// round 1
// baseline (speedup 1.0000x reference)
#include <cuda_runtime.h>
#include <math.h>

#define B_ 4
#define T_ 2048
#define E_ 1024
#define D_ 4
#define BT_ (B_*T_)

// ---------------- scratch (device globals; no allocation allowed) ----------
__device__ float g_ctx[B_*T_*E_];
__device__ float g_gated[B_*T_*E_];
__device__ float g_temporal[B_*T_*E_];
__device__ float g_gate[B_*T_*E_];
__device__ float g_sg[B_*T_*E_];
__device__ float g_h1[BT_*256];
__device__ float g_mod[BT_*4];

// ---------------- helpers --------------------------------------------------
__device__ __forceinline__ float sigmoidf_(float x) { return 1.0f / (1.0f + expf(-x)); }
__device__ __forceinline__ float geluf_(float x) {
    return 0.5f * x * (1.0f + erff(x * 0.70710678118654752440f));
}

// ---------------- EMA over T for ctx ---------------------------------------
// thread per (b,e): 4096 threads, unroll 8 for MLP.
__global__ void ema_ctx_kernel(const float* __restrict__ x,
                               const float* __restrict__ tau_ctx,
                               float* __restrict__ ctx) {
    int tid = blockIdx.x * blockDim.x + threadIdx.x;
    if (tid >= B_ * E_) return;
    int e = tid & (E_ - 1);
    int b = tid >> 10;
    float alpha = 1.0f / (1.0f + expf(tau_ctx[0]));   // exp(-softplus(tau))
    size_t base = ((size_t)b * T_) * E_ + e;
    float h = 0.0f;
    for (int t = 0; t < T_; t += 8) {
        float v[8];
#pragma unroll
        for (int i = 0; i < 8; i++) v[i] = __ldg(&x[base + (size_t)(t + i) * E_]);
#pragma unroll
        for (int i = 0; i < 8; i++) {
            h = fmaf(alpha, h, v[i]);
            ctx[base + (size_t)(t + i) * E_] = h;
        }
    }
}

// ---------------- 4 modulated EMAs + softmax blend -> temporal --------------
// thread per (b,e); 4 independent EMA chains in registers (ILP), traces never
// hit memory.
__global__ void ema_traces_kernel(const float* __restrict__ gated,
                                  const float* __restrict__ mod,      // (BT,4)
                                  const float* __restrict__ tau_raws, // (4,)
                                  const float* __restrict__ blend,    // (4,E)
                                  float* __restrict__ temporal) {
    int tid = blockIdx.x * blockDim.x + threadIdx.x;
    if (tid >= B_ * E_) return;
    int e = tid & (E_ - 1);
    int b = tid >> 10;

    float al[4];
#pragma unroll
    for (int d = 0; d < 4; d++) al[d] = 1.0f / (1.0f + expf(tau_raws[d]));

    // softmax over d of blend[d][e]
    float bl[4];
#pragma unroll
    for (int d = 0; d < 4; d++) bl[d] = blend[d * E_ + e];
    float mx = fmaxf(fmaxf(bl[0], bl[1]), fmaxf(bl[2], bl[3]));
    float bw[4], sum = 0.0f;
#pragma unroll
    for (int d = 0; d < 4; d++) { bw[d] = expf(bl[d] - mx); sum += bw[d]; }
    float inv = 1.0f / sum;
#pragma unroll
    for (int d = 0; d < 4; d++) bw[d] *= inv;

    size_t base = ((size_t)b * T_) * E_ + e;
    const float4* mod4 = reinterpret_cast<const float4*>(mod);
    size_t mbase = (size_t)b * T_;

    float h0 = 0.f, h1 = 0.f, h2 = 0.f, h3 = 0.f;
    for (int t = 0; t < T_; t += 4) {
        float g[4]; float4 mm[4];
#pragma unroll
        for (int i = 0; i < 4; i++) {
            g[i]  = __ldg(&gated[base + (size_t)(t + i) * E_]);
            mm[i] = __ldg(&mod4[mbase + t + i]);
        }
#pragma unroll
        for (int i = 0; i < 4; i++) {
            h0 = fmaf(al[0], h0, g[i] * mm[i].x);
            h1 = fmaf(al[1], h1, g[i] * mm[i].y);
            h2 = fmaf(al[2], h2, g[i] * mm[i].z);
            h3 = fmaf(al[3], h3, g[i] * mm[i].w);
            temporal[base + (size_t)(t + i) * E_] =
                bw[0] * h0 + bw[1] * h1 + bw[2] * h2 + bw[3] * h3;
        }
    }
}

// ---------------- generic fp32 GEMM  C = epi(A @ W^T + bias) ----------------
// A: (M,K) row-major (optionally concat of A||A2 along K, each with row
// stride KA). W: (N,K) row-major. 128x128x16 tile, 256 threads, 8x8/thread.
// mode: 0 none, 1 sigmoid(.)*extra (gated), 2 gelu, 3 sigmoid, 4 gelu(.)*extra
__global__ void __launch_bounds__(256)
gemm_tn(const float* __restrict__ A, const float* __restrict__ A2, int KA,
        const float* __restrict__ W, const float* __restrict__ bias,
        const float* __restrict__ extra, float* __restrict__ C,
        int M, int N, int K, int mode) {
    __shared__ float As[16][128 + 4];
    __shared__ float Bs[16][128 + 4];

    int tid = threadIdx.x;
    int bm = blockIdx.y * 128;
    int bn = blockIdx.x * 128;
    int ty = tid / 16;           // 0..15
    int tx = tid % 16;           // 0..15

    int lrow = tid >> 2;         // 0..63
    int lc4  = (tid & 3) * 4;    // 0,4,8,12

    float acc[8][8];
#pragma unroll
    for (int i = 0; i < 8; i++)
#pragma unroll
        for (int j = 0; j < 8; j++) acc[i][j] = 0.0f;

    for (int k0 = 0; k0 < K; k0 += 16) {
        // ---- A tile (transposed into As[k][m]) ----
        {
            const float* src = A;
            int c = k0 + lc4;
            if (A2 != nullptr && c >= KA) { src = A2; c -= KA; }
#pragma unroll
            for (int r = 0; r < 2; r++) {
                int row = bm + lrow + r * 64;
                float4 v = *reinterpret_cast<const float4*>(src + (size_t)row * KA + c);
                As[lc4 + 0][lrow + r * 64] = v.x;
                As[lc4 + 1][lrow + r * 64] = v.y;
                As[lc4 + 2][lrow + r * 64] = v.z;
                As[lc4 + 3][lrow + r * 64] = v.w;
            }
        }
        // ---- B tile: Bs[k][n] = W[(bn+n)*K + k0+k] ----
        {
#pragma unroll
            for (int r = 0; r < 2; r++) {
                int n = lrow + r * 64;
                float4 v = *reinterpret_cast<const float4*>(W + (size_t)(bn + n) * K + k0 + lc4);
                Bs[lc4 + 0][n] = v.x;
                Bs[lc4 + 1][n] = v.y;
                Bs[lc4 + 2][n] = v.z;
                Bs[lc4 + 3][n] = v.w;
            }
        }
        __syncthreads();

#pragma unroll
        for (int kk = 0; kk < 16; kk++) {
            float a[8], b[8];
#pragma unroll
            for (int i = 0; i < 8; i++) a[i] = As[kk][ty * 8 + i];
#pragma unroll
            for (int j = 0; j < 8; j++) b[j] = Bs[kk][tx * 8 + j];
#pragma unroll
            for (int i = 0; i < 8; i++)
#pragma unroll
                for (int j = 0; j < 8; j++) acc[i][j] = fmaf(a[i], b[j], acc[i][j]);
        }
        __syncthreads();
    }

    // ---- epilogue ----
#pragma unroll
    for (int i = 0; i < 8; i++) {
        int m = bm + ty * 8 + i;
#pragma unroll
        for (int j = 0; j < 8; j++) {
            int n = bn + tx * 8 + j;
            float v = acc[i][j];
            if (bias != nullptr) v += __ldg(&bias[n]);
            size_t idx = (size_t)m * N + n;
            switch (mode) {
                case 0: break;
                case 1: v = sigmoidf_(v) * __ldg(&extra[idx]); break;
                case 2: v = geluf_(v); break;
                case 3: v = sigmoidf_(v); break;
                case 4: v = geluf_(v) * __ldg(&extra[idx]); break;
            }
            C[idx] = v;
        }
    }
}

// ---------------- mod = 0.5 + sigmoid(h1 @ Wn2^T + bn2) ---------------------
// one warp per row (BT rows), K=256, N=4.
__global__ void mod_kernel(const float* __restrict__ h1,
                           const float* __restrict__ Wn2,  // (4,256)
                           const float* __restrict__ bn2,  // (4,)
                           float* __restrict__ mod) {
    int warp = (blockIdx.x * blockDim.x + threadIdx.x) >> 5;
    int lane = threadIdx.x & 31;
    if (warp >= BT_) return;
    const float* hr = h1 + (size_t)warp * 256;
    float a0 = 0.f, a1 = 0.f, a2 = 0.f, a3 = 0.f;
    for (int k = lane; k < 256; k += 32) {
        float hv = __ldg(&hr[k]);
        a0 = fmaf(hv, __ldg(&Wn2[k]),       a0);
        a1 = fmaf(hv, __ldg(&Wn2[256 + k]), a1);
        a2 = fmaf(hv, __ldg(&Wn2[512 + k]), a2);
        a3 = fmaf(hv, __ldg(&Wn2[768 + k]), a3);
    }
#pragma unroll
    for (int o = 16; o > 0; o >>= 1) {
        a0 += __shfl_xor_sync(0xffffffff, a0, o);
        a1 += __shfl_xor_sync(0xffffffff, a1, o);
        a2 += __shfl_xor_sync(0xffffffff, a2, o);
        a3 += __shfl_xor_sync(0xffffffff, a3, o);
    }
    if (lane == 0) {
        mod[(size_t)warp * 4 + 0] = 0.5f + sigmoidf_(a0 + bn2[0]);
        mod[(size_t)warp * 4 + 1] = 0.5f + sigmoidf_(a1 + bn2[1]);
        mod[(size_t)warp * 4 + 2] = 0.5f + sigmoidf_(a2 + bn2[2]);
        mod[(size_t)warp * 4 + 3] = 0.5f + sigmoidf_(a3 + bn2[3]);
    }
}

// ---------------- in-place LayerNorm over E per row --------------------------
__global__ void ln_kernel(float* __restrict__ out,
                          const float* __restrict__ gamma,
                          const float* __restrict__ beta) {
    int row = blockIdx.x;
    float* p = out + (size_t)row * E_;
    int tid = threadIdx.x;          // 256
    float v[4];
    float s = 0.f, ss = 0.f;
#pragma unroll
    for (int i = 0; i < 4; i++) {
        v[i] = p[tid + i * 256];
        s += v[i];
        ss += v[i] * v[i];
    }
#pragma unroll
    for (int o = 16; o > 0; o >>= 1) {
        s  += __shfl_down_sync(0xffffffff, s,  o);
        ss += __shfl_down_sync(0xffffffff, ss, o);
    }
    __shared__ float shs[8], shss[8];
    __shared__ float mu_s, inv_s;
    int wid = tid >> 5, lane = tid & 31;
    if (lane == 0) { shs[wid] = s; shss[wid] = ss; }
    __syncthreads();
    if (tid == 0) {
        float S = 0.f, SS = 0.f;
#pragma unroll
        for (int w = 0; w < 8; w++) { S += shs[w]; SS += shss[w]; }
        float mu  = S / (float)E_;
        float var = SS / (float)E_ - mu * mu;
        mu_s = mu;
        inv_s = rsqrtf(var + 1e-5f);
    }
    __syncthreads();
    float mu = mu_s, iv = inv_s;
#pragma unroll
    for (int i = 0; i < 4; i++) {
        int c = tid + i * 256;
        p[c] = (v[i] - mu) * iv * __ldg(&gamma[c]) + __ldg(&beta[c]);
    }
}

// ---------------- launch -----------------------------------------------------
extern "C" void kernel_launch(void* const* d_in, const int* in_sizes, int n_in,
                              void* d_out, int out_size) {
    const float* x        = (const float*)d_in[0];
    const float* tau_ctx  = (const float*)d_in[1];
    const float* tau_raws = (const float*)d_in[2];
    const float* Wg       = (const float*)d_in[3];
    const float* bg       = (const float*)d_in[4];
    const float* Wn1      = (const float*)d_in[5];
    const float* bn1      = (const float*)d_in[6];
    const float* Wn2      = (const float*)d_in[7];
    const float* bn2      = (const float*)d_in[8];
    const float* blend    = (const float*)d_in[9];
    const float* Wsoma    = (const float*)d_in[10];
    const float* bsoma    = (const float*)d_in[11];
    const float* Wtemp    = (const float*)d_in[12];
    const float* btemp    = (const float*)d_in[13];
    const float* Wout     = (const float*)d_in[14];
    const float* gamma    = (const float*)d_in[15];
    const float* beta     = (const float*)d_in[16];
    float* out = (float*)d_out;

    float *ctx, *gated, *temporal, *gate, *sg, *h1, *mod;
    cudaGetSymbolAddress((void**)&ctx,      g_ctx);
    cudaGetSymbolAddress((void**)&gated,    g_gated);
    cudaGetSymbolAddress((void**)&temporal, g_temporal);
    cudaGetSymbolAddress((void**)&gate,     g_gate);
    cudaGetSymbolAddress((void**)&sg,       g_sg);
    cudaGetSymbolAddress((void**)&h1,       g_h1);
    cudaGetSymbolAddress((void**)&mod,      g_mod);

    // 1) ctx = EMA(x, tau_ctx)
    ema_ctx_kernel<<<(B_ * E_) / 256, 256>>>(x, tau_ctx, ctx);

    // 2) gated = x * sigmoid([x,ctx] @ Wg^T + bg)   (M=BT, N=E, K=2E)
    {
        dim3 grid(E_ / 128, BT_ / 128);
        gemm_tn<<<grid, 256>>>(x, ctx, E_, Wg, bg, x, gated, BT_, E_, 2 * E_, 1);
    }

    // 3) h1 = gelu(x @ Wn1^T + bn1)   (M=BT, N=256, K=E)
    {
        dim3 grid(256 / 128, BT_ / 128);
        gemm_tn<<<grid, 256>>>(x, nullptr, E_, Wn1, bn1, nullptr, h1, BT_, 256, E_, 2);
    }

    // 4) mod = 0.5 + sigmoid(h1 @ Wn2^T + bn2)
    mod_kernel<<<(BT_ * 32) / 256, 256>>>(h1, Wn2, bn2, mod);

    // 5) temporal = sum_d softmax(blend)[d] * EMA_d(gated * mod[:,d])
    ema_traces_kernel<<<(B_ * E_) / 256, 256>>>(gated, mod, tau_raws, blend, temporal);

    // 6) gate = sigmoid(temporal @ Wtemp^T + btemp)
    {
        dim3 grid(E_ / 128, BT_ / 128);
        gemm_tn<<<grid, 256>>>(temporal, nullptr, E_, Wtemp, btemp, nullptr, gate, BT_, E_, E_, 3);
    }

    // 7) sg = gelu(x @ Wsoma^T + bsoma) * gate
    {
        dim3 grid(E_ / 128, BT_ / 128);
        gemm_tn<<<grid, 256>>>(x, nullptr, E_, Wsoma, bsoma, gate, sg, BT_, E_, E_, 4);
    }

    // 8) out = sg @ Wout^T
    {
        dim3 grid(E_ / 128, BT_ / 128);
        gemm_tn<<<grid, 256>>>(sg, nullptr, E_, Wout, nullptr, nullptr, out, BT_, E_, E_, 0);
    }

    // 9) LayerNorm in place
    ln_kernel<<<BT_, 256>>>(out, gamma, beta);
}

// round 3
// speedup vs baseline: 1.1223x; 1.1223x over previous
#include <cuda_runtime.h>
#include <math.h>
#include <cstdint>
#include <mma.h>

using namespace nvcuda;

#define B_ 4
#define T_ 2048
#define E_ 1024
#define BT_ (B_*T_)

// ---------------- scratch (device globals; no allocation allowed) ----------
__device__ float g_ctx[BT_*E_];
__device__ float g_gated[BT_*E_];
__device__ float g_temporal[BT_*E_];
__device__ float g_gate[BT_*E_];
__device__ float g_sg[BT_*E_];
__device__ float g_h1[BT_*256];
__device__ float g_mod[BT_*4];

// ---------------- helpers --------------------------------------------------
__device__ __forceinline__ float sigmoidf_(float x) { return 1.0f / (1.0f + expf(-x)); }
__device__ __forceinline__ float geluf_(float x) {
    return 0.5f * x * (1.0f + erff(x * 0.70710678118654752440f));
}

// ---------------- EMA over T for ctx ---------------------------------------
__global__ void ema_ctx_kernel(const float* __restrict__ x,
                               const float* __restrict__ tau_ctx,
                               float* __restrict__ ctx) {
    int tid = blockIdx.x * blockDim.x + threadIdx.x;
    if (tid >= B_ * E_) return;
    int e = tid & (E_ - 1);
    int b = tid >> 10;
    float alpha = 1.0f / (1.0f + expf(tau_ctx[0]));   // exp(-softplus(tau))
    size_t base = ((size_t)b * T_) * E_ + e;
    float h = 0.0f;
    for (int t = 0; t < T_; t += 8) {
        float v[8];
#pragma unroll
        for (int i = 0; i < 8; i++) v[i] = __ldg(&x[base + (size_t)(t + i) * E_]);
#pragma unroll
        for (int i = 0; i < 8; i++) {
            h = fmaf(alpha, h, v[i]);
            ctx[base + (size_t)(t + i) * E_] = h;
        }
    }
}

// ---------------- 4 modulated EMAs + softmax blend -> temporal --------------
__global__ void ema_traces_kernel(const float* __restrict__ gated,
                                  const float* __restrict__ mod,      // (BT,4)
                                  const float* __restrict__ tau_raws, // (4,)
                                  const float* __restrict__ blend,    // (4,E)
                                  float* __restrict__ temporal) {
    int tid = blockIdx.x * blockDim.x + threadIdx.x;
    if (tid >= B_ * E_) return;
    int e = tid & (E_ - 1);
    int b = tid >> 10;

    float al[4];
#pragma unroll
    for (int d = 0; d < 4; d++) al[d] = 1.0f / (1.0f + expf(tau_raws[d]));

    float bl[4];
#pragma unroll
    for (int d = 0; d < 4; d++) bl[d] = blend[d * E_ + e];
    float mx = fmaxf(fmaxf(bl[0], bl[1]), fmaxf(bl[2], bl[3]));
    float bw[4], sum = 0.0f;
#pragma unroll
    for (int d = 0; d < 4; d++) { bw[d] = expf(bl[d] - mx); sum += bw[d]; }
    float inv = 1.0f / sum;
#pragma unroll
    for (int d = 0; d < 4; d++) bw[d] *= inv;

    size_t base = ((size_t)b * T_) * E_ + e;
    const float4* mod4 = reinterpret_cast<const float4*>(mod);
    size_t mbase = (size_t)b * T_;

    float h0 = 0.f, h1 = 0.f, h2 = 0.f, h3 = 0.f;
    for (int t = 0; t < T_; t += 4) {
        float g[4]; float4 mm[4];
#pragma unroll
        for (int i = 0; i < 4; i++) {
            g[i]  = __ldg(&gated[base + (size_t)(t + i) * E_]);
            mm[i] = __ldg(&mod4[mbase + t + i]);
        }
#pragma unroll
        for (int i = 0; i < 4; i++) {
            h0 = fmaf(al[0], h0, g[i] * mm[i].x);
            h1 = fmaf(al[1], h1, g[i] * mm[i].y);
            h2 = fmaf(al[2], h2, g[i] * mm[i].z);
            h3 = fmaf(al[3], h3, g[i] * mm[i].w);
            temporal[base + (size_t)(t + i) * E_] =
                bw[0] * h0 + bw[1] * h1 + bw[2] * h2 + bw[3] * h3;
        }
    }
}

// ---------------- tf32 wmma GEMM  C = epi(A @ W^T + bias) -------------------
// A: (M,K) fp32 row-major (optionally concat A||A2 along K, each row stride KA).
// W: (N,K) fp32 row-major. CTA 128x128, K-chunk 32, 8 warps (warp tile 32x64),
// double-buffered smem, tf32 conversion during gmem->smem.
// mode: 0 none, 1 sigmoid(.)*extra, 2 gelu, 3 sigmoid, 4 gelu(.)*extra
static constexpr int LDA = 36;                     // 128x36 floats, pad kills most conflicts
static constexpr int STAGE_FLOATS = 128 * LDA;     // per operand tile
static constexpr int STAGE_BYTES  = 2 * STAGE_FLOATS * 4;   // A+B = 36864
static constexpr int LDC = 132;
static constexpr int DYN_SMEM = 2 * STAGE_BYTES;   // 73728 (>= 128*132*4 = 67584 for epilogue)

__global__ void __launch_bounds__(256)
gemm_wm(const float* __restrict__ A, const float* __restrict__ A2, int KA,
        const float* __restrict__ W, const float* __restrict__ bias,
        const float* __restrict__ extra, float* __restrict__ C,
        int N, int K, int mode) {
    extern __shared__ float smem[];
    int tid = threadIdx.x, wid = tid >> 5;
    int bm = blockIdx.y * 128, bn = blockIdx.x * 128;
    int wm = (wid & 3) * 32;     // warp M offset in tile
    int wn = (wid >> 2) * 64;    // warp N offset in tile

    wmma::fragment<wmma::accumulator, 16, 16, 8, float> acc[2][4];
#pragma unroll
    for (int i = 0; i < 2; i++)
#pragma unroll
        for (int j = 0; j < 4; j++) wmma::fill_fragment(acc[i][j], 0.0f);

    const int NC = K / 32;

    auto load_chunk = [&](int c, int s) {
        int k0 = c * 32;
        const float* srcA = A; int ka = k0;
        if (A2 != nullptr && k0 >= KA) { srcA = A2; ka = k0 - KA; }
        float* As = smem + s * (STAGE_BYTES / 4);
        float* Bs = As + STAGE_FLOATS;
#pragma unroll
        for (int t = 0; t < 4; t++) {
            int idx = tid + t * 256;
            int row = idx >> 3, c4 = (idx & 7) * 4;
            float4 va = *reinterpret_cast<const float4*>(srcA + (size_t)(bm + row) * KA + ka + c4);
            float* pa = As + row * LDA + c4;
            pa[0] = wmma::__float_to_tf32(va.x);
            pa[1] = wmma::__float_to_tf32(va.y);
            pa[2] = wmma::__float_to_tf32(va.z);
            pa[3] = wmma::__float_to_tf32(va.w);
            float4 vb = *reinterpret_cast<const float4*>(W + (size_t)(bn + row) * K + k0 + c4);
            float* pb = Bs + row * LDA + c4;
            pb[0] = wmma::__float_to_tf32(vb.x);
            pb[1] = wmma::__float_to_tf32(vb.y);
            pb[2] = wmma::__float_to_tf32(vb.z);
            pb[3] = wmma::__float_to_tf32(vb.w);
        }
    };

    load_chunk(0, 0);
    __syncthreads();

    for (int c = 0; c < NC; c++) {
        int s = c & 1;
        if (c + 1 < NC) load_chunk(c + 1, 1 - s);

        const float* As = smem + s * (STAGE_BYTES / 4);
        const float* Bs = As + STAGE_FLOATS;
#pragma unroll
        for (int ks = 0; ks < 4; ks++) {
            int k0 = ks * 8;
            wmma::fragment<wmma::matrix_a, 16, 16, 8, wmma::precision::tf32, wmma::row_major> af[2];
            wmma::fragment<wmma::matrix_b, 16, 16, 8, wmma::precision::tf32, wmma::col_major> bf[4];
#pragma unroll
            for (int i = 0; i < 2; i++)
                wmma::load_matrix_sync(af[i], As + (wm + i * 16) * LDA + k0, LDA);
#pragma unroll
            for (int j = 0; j < 4; j++)
                wmma::load_matrix_sync(bf[j], Bs + (wn + j * 16) * LDA + k0, LDA);
#pragma unroll
            for (int i = 0; i < 2; i++)
#pragma unroll
                for (int j = 0; j < 4; j++)
                    wmma::mma_sync(acc[i][j], af[i], bf[j], acc[i][j]);
        }
        __syncthreads();
    }

    // -------- epilogue: frags -> smem -> fused activation -> float4 STG -----
    float* Cs = smem;
#pragma unroll
    for (int i = 0; i < 2; i++)
#pragma unroll
        for (int j = 0; j < 4; j++)
            wmma::store_matrix_sync(Cs + (wm + i * 16) * LDC + wn + j * 16,
                                    acc[i][j], LDC, wmma::mem_row_major);
    __syncthreads();

    for (int t = tid; t < 128 * 32; t += 256) {
        int r = t >> 5, c0 = (t & 31) * 4;
        const float* rg = Cs + r * LDC + c0;
        int m = bm + r, n = bn + c0;
        size_t oidx = (size_t)m * N + n;
        float exv[4] = {0.f, 0.f, 0.f, 0.f};
        if (mode == 1 || mode == 4) {
            float4 ex = *reinterpret_cast<const float4*>(extra + oidx);
            exv[0] = ex.x; exv[1] = ex.y; exv[2] = ex.z; exv[3] = ex.w;
        }
        float v[4];
#pragma unroll
        for (int i = 0; i < 4; i++) {
            v[i] = rg[i];
            if (bias != nullptr) v[i] += __ldg(&bias[n + i]);
            switch (mode) {
                case 0: break;
                case 1: v[i] = sigmoidf_(v[i]) * exv[i]; break;
                case 2: v[i] = geluf_(v[i]); break;
                case 3: v[i] = sigmoidf_(v[i]); break;
                case 4: v[i] = geluf_(v[i]) * exv[i]; break;
            }
        }
        *reinterpret_cast<float4*>(C + oidx) = make_float4(v[0], v[1], v[2], v[3]);
    }
}

// ---------------- mod = 0.5 + sigmoid(h1 @ Wn2^T + bn2) ---------------------
__global__ void mod_kernel(const float* __restrict__ h1,
                           const float* __restrict__ Wn2,  // (4,256)
                           const float* __restrict__ bn2,  // (4,)
                           float* __restrict__ mod) {
    int warp = (blockIdx.x * blockDim.x + threadIdx.x) >> 5;
    int lane = threadIdx.x & 31;
    if (warp >= BT_) return;
    const float* hr = h1 + (size_t)warp * 256;
    float a0 = 0.f, a1 = 0.f, a2 = 0.f, a3 = 0.f;
    for (int k = lane; k < 256; k += 32) {
        float hv = __ldg(&hr[k]);
        a0 = fmaf(hv, __ldg(&Wn2[k]),       a0);
        a1 = fmaf(hv, __ldg(&Wn2[256 + k]), a1);
        a2 = fmaf(hv, __ldg(&Wn2[512 + k]), a2);
        a3 = fmaf(hv, __ldg(&Wn2[768 + k]), a3);
    }
#pragma unroll
    for (int o = 16; o > 0; o >>= 1) {
        a0 += __shfl_xor_sync(0xffffffff, a0, o);
        a1 += __shfl_xor_sync(0xffffffff, a1, o);
        a2 += __shfl_xor_sync(0xffffffff, a2, o);
        a3 += __shfl_xor_sync(0xffffffff, a3, o);
    }
    if (lane == 0) {
        mod[(size_t)warp * 4 + 0] = 0.5f + sigmoidf_(a0 + bn2[0]);
        mod[(size_t)warp * 4 + 1] = 0.5f + sigmoidf_(a1 + bn2[1]);
        mod[(size_t)warp * 4 + 2] = 0.5f + sigmoidf_(a2 + bn2[2]);
        mod[(size_t)warp * 4 + 3] = 0.5f + sigmoidf_(a3 + bn2[3]);
    }
}

// ---------------- in-place LayerNorm over E per row --------------------------
__global__ void ln_kernel(float* __restrict__ out,
                          const float* __restrict__ gamma,
                          const float* __restrict__ beta) {
    int row = blockIdx.x;
    float* p = out + (size_t)row * E_;
    int tid = threadIdx.x;          // 256
    float v[4];
    float s = 0.f, ss = 0.f;
#pragma unroll
    for (int i = 0; i < 4; i++) {
        v[i] = p[tid + i * 256];
        s += v[i];
        ss += v[i] * v[i];
    }
#pragma unroll
    for (int o = 16; o > 0; o >>= 1) {
        s  += __shfl_down_sync(0xffffffff, s,  o);
        ss += __shfl_down_sync(0xffffffff, ss, o);
    }
    __shared__ float shs[8], shss[8];
    __shared__ float mu_s, inv_s;
    int wid = tid >> 5, lane = tid & 31;
    if (lane == 0) { shs[wid] = s; shss[wid] = ss; }
    __syncthreads();
    if (tid == 0) {
        float S = 0.f, SS = 0.f;
#pragma unroll
        for (int w = 0; w < 8; w++) { S += shs[w]; SS += shss[w]; }
        float mu  = S / (float)E_;
        float var = SS / (float)E_ - mu * mu;
        mu_s = mu;
        inv_s = rsqrtf(var + 1e-5f);
    }
    __syncthreads();
    float mu = mu_s, iv = inv_s;
#pragma unroll
    for (int i = 0; i < 4; i++) {
        int c = tid + i * 256;
        p[c] = (v[i] - mu) * iv * __ldg(&gamma[c]) + __ldg(&beta[c]);
    }
}

// ---------------- launch -----------------------------------------------------
extern "C" void kernel_launch(void* const* d_in, const int* in_sizes, int n_in,
                              void* d_out, int out_size) {
    const float* x        = (const float*)d_in[0];
    const float* tau_ctx  = (const float*)d_in[1];
    const float* tau_raws = (const float*)d_in[2];
    const float* Wg       = (const float*)d_in[3];
    const float* bg       = (const float*)d_in[4];
    const float* Wn1      = (const float*)d_in[5];
    const float* bn1      = (const float*)d_in[6];
    const float* Wn2      = (const float*)d_in[7];
    const float* bn2      = (const float*)d_in[8];
    const float* blend    = (const float*)d_in[9];
    const float* Wsoma    = (const float*)d_in[10];
    const float* bsoma    = (const float*)d_in[11];
    const float* Wtemp    = (const float*)d_in[12];
    const float* btemp    = (const float*)d_in[13];
    const float* Wout     = (const float*)d_in[14];
    const float* gamma    = (const float*)d_in[15];
    const float* beta     = (const float*)d_in[16];
    float* out = (float*)d_out;

    float *ctx, *gated, *temporal, *gate, *sg, *h1, *mod;
    cudaGetSymbolAddress((void**)&ctx,      g_ctx);
    cudaGetSymbolAddress((void**)&gated,    g_gated);
    cudaGetSymbolAddress((void**)&temporal, g_temporal);
    cudaGetSymbolAddress((void**)&gate,     g_gate);
    cudaGetSymbolAddress((void**)&sg,       g_sg);
    cudaGetSymbolAddress((void**)&h1,       g_h1);
    cudaGetSymbolAddress((void**)&mod,      g_mod);

    cudaFuncSetAttribute(gemm_wm, cudaFuncAttributeMaxDynamicSharedMemorySize, DYN_SMEM);

    // 1) ctx = EMA(x, tau_ctx)
    ema_ctx_kernel<<<(B_ * E_) / 256, 256>>>(x, tau_ctx, ctx);

    // 2) gated = x * sigmoid([x,ctx] @ Wg^T + bg)   (M=BT, N=E, K=2E)
    {
        dim3 grid(E_ / 128, BT_ / 128);
        gemm_wm<<<grid, 256, DYN_SMEM>>>(x, ctx, E_, Wg, bg, x, gated, E_, 2 * E_, 1);
    }

    // 3) h1 = gelu(x @ Wn1^T + bn1)   (M=BT, N=256, K=E)
    {
        dim3 grid(256 / 128, BT_ / 128);
        gemm_wm<<<grid, 256, DYN_SMEM>>>(x, nullptr, E_, Wn1, bn1, nullptr, h1, 256, E_, 2);
    }

    // 4) mod = 0.5 + sigmoid(h1 @ Wn2^T + bn2)
    mod_kernel<<<(BT_ * 32) / 256, 256>>>(h1, Wn2, bn2, mod);

    // 5) temporal = sum_d softmax(blend)[d] * EMA_d(gated * mod[:,d])
    ema_traces_kernel<<<(B_ * E_) / 256, 256>>>(gated, mod, tau_raws, blend, temporal);

    // 6) gate = sigmoid(temporal @ Wtemp^T + btemp)
    {
        dim3 grid(E_ / 128, BT_ / 128);
        gemm_wm<<<grid, 256, DYN_SMEM>>>(temporal, nullptr, E_, Wtemp, btemp, nullptr, gate, E_, E_, 3);
    }

    // 7) sg = gelu(x @ Wsoma^T + bsoma) * gate
    {
        dim3 grid(E_ / 128, BT_ / 128);
        gemm_wm<<<grid, 256, DYN_SMEM>>>(x, nullptr, E_, Wsoma, bsoma, gate, sg, E_, E_, 4);
    }

    // 8) out = sg @ Wout^T
    {
        dim3 grid(E_ / 128, BT_ / 128);
        gemm_wm<<<grid, 256, DYN_SMEM>>>(sg, nullptr, E_, Wout, nullptr, nullptr, out, E_, E_, 0);
    }

    // 9) LayerNorm in place
    ln_kernel<<<BT_, 256>>>(out, gamma, beta);
}

// round 4
// speedup vs baseline: 3.1378x; 2.7958x over previous
#include <cuda_runtime.h>
#include <math.h>
#include <cstdint>

#define B_ 4
#define T_ 2048
#define E_ 1024
#define BT_ (B_*T_)
#define SEG_ 16
#define SEGL_ (T_/SEG_)   // 128

// ---------------- scratch (device globals; no allocation allowed) ----------
__device__ float g_ctx[BT_*E_];
__device__ float g_gated[BT_*E_];
__device__ float g_temporal[BT_*E_];
__device__ float g_gate[BT_*E_];
__device__ float g_sg[BT_*E_];
__device__ float g_h1[BT_*256];
__device__ float g_mod[BT_*4];
__device__ float g_seg[B_*SEG_*E_];
__device__ float g_seg4[4*B_*SEG_*E_];

// ---------------- helpers --------------------------------------------------
__device__ __forceinline__ float sigmoidf_(float x) { return 1.0f / (1.0f + expf(-x)); }
__device__ __forceinline__ float geluf_(float x) {
    return 0.5f * x * (1.0f + erff(x * 0.70710678118654752440f));
}
__device__ __forceinline__ uint32_t to_tf32(float x) {
    uint32_t r;
    asm("cvt.rna.tf32.f32 %0, %1;" : "=r"(r) : "f"(x));
    return r;
}

// ============================================================================
// Segmented EMA for ctx: h_t = alpha*h_{t-1} + x_t
// ============================================================================
__global__ void ema_ctx_p1(const float* __restrict__ x,
                           const float* __restrict__ tau_ctx,
                           float* __restrict__ seg) {
    int tid = blockIdx.x * blockDim.x + threadIdx.x;    // B*E*SEG threads
    if (tid >= B_ * E_ * SEG_) return;
    int e = tid & (E_ - 1);
    int s = (tid >> 10) & (SEG_ - 1);
    int b = tid >> 14;
    float alpha = 1.0f / (1.0f + expf(tau_ctx[0]));
    size_t base = ((size_t)(b * T_ + s * SEGL_)) * E_ + e;
    float h = 0.0f;
    for (int t = 0; t < SEGL_; t += 8) {
        float v[8];
#pragma unroll
        for (int i = 0; i < 8; i++) v[i] = __ldg(&x[base + (size_t)(t + i) * E_]);
#pragma unroll
        for (int i = 0; i < 8; i++) h = fmaf(alpha, h, v[i]);
    }
    seg[(b * SEG_ + s) * E_ + e] = h;
}

__global__ void ema_ctx_p2(const float* __restrict__ tau_ctx,
                           float* __restrict__ seg) {
    int tid = blockIdx.x * blockDim.x + threadIdx.x;    // B*E threads
    if (tid >= B_ * E_) return;
    int e = tid & (E_ - 1);
    int b = tid >> 10;
    float alpha = 1.0f / (1.0f + expf(tau_ctx[0]));
    float aL = 1.0f;
    for (int k = 0; k < SEGL_; k++) aL *= alpha;
    float carry = 0.0f;
    for (int s = 0; s < SEG_; s++) {
        size_t idx = (size_t)(b * SEG_ + s) * E_ + e;
        float Es = seg[idx];
        seg[idx] = carry;               // state at segment start
        carry = fmaf(aL, carry, Es);
    }
}

__global__ void ema_ctx_p3(const float* __restrict__ x,
                           const float* __restrict__ tau_ctx,
                           const float* __restrict__ seg,
                           float* __restrict__ ctx) {
    int tid = blockIdx.x * blockDim.x + threadIdx.x;
    if (tid >= B_ * E_ * SEG_) return;
    int e = tid & (E_ - 1);
    int s = (tid >> 10) & (SEG_ - 1);
    int b = tid >> 14;
    float alpha = 1.0f / (1.0f + expf(tau_ctx[0]));
    size_t base = ((size_t)(b * T_ + s * SEGL_)) * E_ + e;
    float h = seg[(b * SEG_ + s) * E_ + e];
    for (int t = 0; t < SEGL_; t += 8) {
        float v[8];
#pragma unroll
        for (int i = 0; i < 8; i++) v[i] = __ldg(&x[base + (size_t)(t + i) * E_]);
#pragma unroll
        for (int i = 0; i < 8; i++) {
            h = fmaf(alpha, h, v[i]);
            ctx[base + (size_t)(t + i) * E_] = h;
        }
    }
}

// ============================================================================
// Segmented EMA for the 4 modulated traces + softmax blend
// ============================================================================
__global__ void ema_tr_p1(const float* __restrict__ gated,
                          const float* __restrict__ mod,      // (BT,4)
                          const float* __restrict__ tau_raws, // (4,)
                          float* __restrict__ seg4) {
    int tid = blockIdx.x * blockDim.x + threadIdx.x;
    if (tid >= B_ * E_ * SEG_) return;
    int e = tid & (E_ - 1);
    int s = (tid >> 10) & (SEG_ - 1);
    int b = tid >> 14;
    float al[4];
#pragma unroll
    for (int d = 0; d < 4; d++) al[d] = 1.0f / (1.0f + expf(tau_raws[d]));
    size_t base = ((size_t)(b * T_ + s * SEGL_)) * E_ + e;
    const float4* mod4 = reinterpret_cast<const float4*>(mod);
    size_t mbase = (size_t)b * T_ + s * SEGL_;
    float h0 = 0.f, h1 = 0.f, h2 = 0.f, h3 = 0.f;
    for (int t = 0; t < SEGL_; t += 4) {
        float g[4]; float4 mm[4];
#pragma unroll
        for (int i = 0; i < 4; i++) {
            g[i]  = __ldg(&gated[base + (size_t)(t + i) * E_]);
            mm[i] = __ldg(&mod4[mbase + t + i]);
        }
#pragma unroll
        for (int i = 0; i < 4; i++) {
            h0 = fmaf(al[0], h0, g[i] * mm[i].x);
            h1 = fmaf(al[1], h1, g[i] * mm[i].y);
            h2 = fmaf(al[2], h2, g[i] * mm[i].z);
            h3 = fmaf(al[3], h3, g[i] * mm[i].w);
        }
    }
    size_t o = (size_t)(b * SEG_ + s) * E_ + e;
    seg4[0 * (B_*SEG_*E_) + o] = h0;
    seg4[1 * (B_*SEG_*E_) + o] = h1;
    seg4[2 * (B_*SEG_*E_) + o] = h2;
    seg4[3 * (B_*SEG_*E_) + o] = h3;
}

__global__ void ema_tr_p2(const float* __restrict__ tau_raws,
                          float* __restrict__ seg4) {
    int tid = blockIdx.x * blockDim.x + threadIdx.x;
    if (tid >= B_ * E_) return;
    int e = tid & (E_ - 1);
    int b = tid >> 10;
#pragma unroll
    for (int d = 0; d < 4; d++) {
        float alpha = 1.0f / (1.0f + expf(tau_raws[d]));
        float aL = 1.0f;
        for (int k = 0; k < SEGL_; k++) aL *= alpha;
        float carry = 0.0f;
        for (int s = 0; s < SEG_; s++) {
            size_t idx = (size_t)d * (B_*SEG_*E_) + (size_t)(b * SEG_ + s) * E_ + e;
            float Es = seg4[idx];
            seg4[idx] = carry;
            carry = fmaf(aL, carry, Es);
        }
    }
}

__global__ void ema_tr_p3(const float* __restrict__ gated,
                          const float* __restrict__ mod,
                          const float* __restrict__ tau_raws,
                          const float* __restrict__ blend,    // (4,E)
                          const float* __restrict__ seg4,
                          float* __restrict__ temporal) {
    int tid = blockIdx.x * blockDim.x + threadIdx.x;
    if (tid >= B_ * E_ * SEG_) return;
    int e = tid & (E_ - 1);
    int s = (tid >> 10) & (SEG_ - 1);
    int b = tid >> 14;

    float al[4];
#pragma unroll
    for (int d = 0; d < 4; d++) al[d] = 1.0f / (1.0f + expf(tau_raws[d]));

    float bl[4];
#pragma unroll
    for (int d = 0; d < 4; d++) bl[d] = blend[d * E_ + e];
    float mx = fmaxf(fmaxf(bl[0], bl[1]), fmaxf(bl[2], bl[3]));
    float bw[4], sum = 0.0f;
#pragma unroll
    for (int d = 0; d < 4; d++) { bw[d] = expf(bl[d] - mx); sum += bw[d]; }
    float inv = 1.0f / sum;
#pragma unroll
    for (int d = 0; d < 4; d++) bw[d] *= inv;

    size_t base = ((size_t)(b * T_ + s * SEGL_)) * E_ + e;
    const float4* mod4 = reinterpret_cast<const float4*>(mod);
    size_t mbase = (size_t)b * T_ + s * SEGL_;
    size_t o = (size_t)(b * SEG_ + s) * E_ + e;
    float h0 = seg4[0 * (B_*SEG_*E_) + o];
    float h1 = seg4[1 * (B_*SEG_*E_) + o];
    float h2 = seg4[2 * (B_*SEG_*E_) + o];
    float h3 = seg4[3 * (B_*SEG_*E_) + o];

    for (int t = 0; t < SEGL_; t += 4) {
        float g[4]; float4 mm[4];
#pragma unroll
        for (int i = 0; i < 4; i++) {
            g[i]  = __ldg(&gated[base + (size_t)(t + i) * E_]);
            mm[i] = __ldg(&mod4[mbase + t + i]);
        }
#pragma unroll
        for (int i = 0; i < 4; i++) {
            h0 = fmaf(al[0], h0, g[i] * mm[i].x);
            h1 = fmaf(al[1], h1, g[i] * mm[i].y);
            h2 = fmaf(al[2], h2, g[i] * mm[i].z);
            h3 = fmaf(al[3], h3, g[i] * mm[i].w);
            temporal[base + (size_t)(t + i) * E_] =
                bw[0] * h0 + bw[1] * h1 + bw[2] * h2 + bw[3] * h3;
        }
    }
}

// ============================================================================
// tf32 mma.sync GEMM  C = epi(A @ W^T + bias)
// A: (M,K) fp32 row-major (optionally A||A2 concat along K, row stride KA).
// W: (N,K) fp32 row-major. CTA 128x128, K-chunk 32, 8 warps (warp 64Mx32N).
// Smem holds tiles in FRAGMENT-NATIVE layout (pad 33 lanes per (block,kstep)):
//   A: ((mb*4+ks)*33 + lane)*4 floats  -> one LDS.128 per fragment
//   B: ((nb*4+ks)*33 + lane)*2 floats  -> one LDS.64  per fragment
// mode: 0 none, 1 sigmoid(.)*extra, 2 gelu, 3 sigmoid, 4 gelu(.)*extra
// ============================================================================
static constexpr int STAGE_FLOATS = 2 * 32 * 33 * 4;   // A(4224) + B(4224) = 8448
static constexpr int LDC = 136;
static constexpr int DYN_SMEM = 128 * LDC * 4;          // 69632 >= 2*STAGE*4=67584

__global__ void __launch_bounds__(256)
gemm_mma(const float* __restrict__ A, const float* __restrict__ A2, int KA,
         const float* __restrict__ W, const float* __restrict__ bias,
         const float* __restrict__ extra, float* __restrict__ C,
         int N, int K, int mode) {
    extern __shared__ float smem[];
    int tid = threadIdx.x, wid = tid >> 5, lane = tid & 31;
    int bm = blockIdx.y * 128, bn = blockIdx.x * 128;
    int wm = wid & 1;        // 0/1: M half (64 rows)
    int wn = wid >> 1;       // 0..3: N quarter (32 cols)

    float acc[4][4][4];
#pragma unroll
    for (int i = 0; i < 4; i++)
#pragma unroll
        for (int j = 0; j < 4; j++)
#pragma unroll
            for (int r = 0; r < 4; r++) acc[i][j][r] = 0.0f;

    const int NC = K / 32;

    auto load_chunk = [&](int c, int s) {
        int k0 = c * 32;
        const float* srcA = A; int ka = k0;
        if (A2 != nullptr && k0 >= KA) { srcA = A2; ka = k0 - KA; }
        float* As = smem + s * STAGE_FLOATS;
        float* Bs = As + 32 * 33 * 4;
#pragma unroll
        for (int t = 0; t < 4; t++) {
            int idx = tid + t * 256;
            int row = idx >> 3;
            int c4  = (idx & 7) * 4;
            int ks = c4 >> 3, cp = (c4 >> 2) & 1;
            // ---- A ----
            float4 va = __ldg(reinterpret_cast<const float4*>(
                srcA + (size_t)(bm + row) * KA + ka + c4));
            int mb = row >> 4, r = row & 15;
            int hi = r >> 3, rlo = r & 7;
            float* pa = As + ((mb * 4 + ks) * 33 + rlo * 4) * 4 + (hi + 2 * cp);
            pa[0]  = __uint_as_float(to_tf32(va.x));
            pa[4]  = __uint_as_float(to_tf32(va.y));
            pa[8]  = __uint_as_float(to_tf32(va.z));
            pa[12] = __uint_as_float(to_tf32(va.w));
            // ---- B ----
            float4 vb = __ldg(reinterpret_cast<const float4*>(
                W + (size_t)(bn + row) * K + k0 + c4));
            int nb = row >> 3, nlo = row & 7;
            float* pb = Bs + ((nb * 4 + ks) * 33 + nlo * 4) * 2 + cp;
            pb[0] = __uint_as_float(to_tf32(vb.x));
            pb[2] = __uint_as_float(to_tf32(vb.y));
            pb[4] = __uint_as_float(to_tf32(vb.z));
            pb[6] = __uint_as_float(to_tf32(vb.w));
        }
    };

    load_chunk(0, 0);
    __syncthreads();

    for (int c = 0; c < NC; c++) {
        int s = c & 1;
        if (c + 1 < NC) load_chunk(c + 1, 1 - s);

        const float* As = smem + s * STAGE_FLOATS;
        const float* Bs = As + 32 * 33 * 4;
#pragma unroll
        for (int ks = 0; ks < 4; ks++) {
            uint32_t a[4][4];
            uint32_t b[4][2];
#pragma unroll
            for (int i = 0; i < 4; i++) {
                float4 v = *reinterpret_cast<const float4*>(
                    As + (((wm * 4 + i) * 4 + ks) * 33 + lane) * 4);
                a[i][0] = __float_as_uint(v.x); a[i][1] = __float_as_uint(v.y);
                a[i][2] = __float_as_uint(v.z); a[i][3] = __float_as_uint(v.w);
            }
#pragma unroll
            for (int j = 0; j < 4; j++) {
                float2 v = *reinterpret_cast<const float2*>(
                    Bs + (((wn * 4 + j) * 4 + ks) * 33 + lane) * 2);
                b[j][0] = __float_as_uint(v.x); b[j][1] = __float_as_uint(v.y);
            }
#pragma unroll
            for (int i = 0; i < 4; i++)
#pragma unroll
                for (int j = 0; j < 4; j++) {
                    asm volatile(
                        "mma.sync.aligned.m16n8k8.row.col.f32.tf32.tf32.f32 "
                        "{%0,%1,%2,%3}, {%4,%5,%6,%7}, {%8,%9}, {%0,%1,%2,%3};"
                        : "+f"(acc[i][j][0]), "+f"(acc[i][j][1]),
                          "+f"(acc[i][j][2]), "+f"(acc[i][j][3])
                        : "r"(a[i][0]), "r"(a[i][1]), "r"(a[i][2]), "r"(a[i][3]),
                          "r"(b[j][0]), "r"(b[j][1]));
                }
        }
        __syncthreads();
    }

    // -------- epilogue: acc frags -> smem -> fused activation -> float4 STG --
    float* Cs = smem;
#pragma unroll
    for (int i = 0; i < 4; i++)
#pragma unroll
        for (int j = 0; j < 4; j++) {
            int r0 = wm * 64 + i * 16 + (lane >> 2);
            int c0 = wn * 32 + j * 8 + (lane & 3) * 2;
            *reinterpret_cast<float2*>(Cs + r0 * LDC + c0) =
                make_float2(acc[i][j][0], acc[i][j][1]);
            *reinterpret_cast<float2*>(Cs + (r0 + 8) * LDC + c0) =
                make_float2(acc[i][j][2], acc[i][j][3]);
        }
    __syncthreads();

    for (int t = tid; t < 128 * 32; t += 256) {
        int r = t >> 5, c0 = (t & 31) * 4;
        const float* rg = Cs + r * LDC + c0;
        int m = bm + r, n = bn + c0;
        size_t oidx = (size_t)m * N + n;
        float exv[4] = {0.f, 0.f, 0.f, 0.f};
        if (mode == 1 || mode == 4) {
            float4 ex = *reinterpret_cast<const float4*>(extra + oidx);
            exv[0] = ex.x; exv[1] = ex.y; exv[2] = ex.z; exv[3] = ex.w;
        }
        float v[4];
#pragma unroll
        for (int i = 0; i < 4; i++) {
            v[i] = rg[i];
            if (bias != nullptr) v[i] += __ldg(&bias[n + i]);
            switch (mode) {
                case 0: break;
                case 1: v[i] = sigmoidf_(v[i]) * exv[i]; break;
                case 2: v[i] = geluf_(v[i]); break;
                case 3: v[i] = sigmoidf_(v[i]); break;
                case 4: v[i] = geluf_(v[i]) * exv[i]; break;
            }
        }
        *reinterpret_cast<float4*>(C + oidx) = make_float4(v[0], v[1], v[2], v[3]);
    }
}

// ---------------- mod = 0.5 + sigmoid(h1 @ Wn2^T + bn2) ---------------------
__global__ void mod_kernel(const float* __restrict__ h1,
                           const float* __restrict__ Wn2,  // (4,256)
                           const float* __restrict__ bn2,  // (4,)
                           float* __restrict__ mod) {
    int warp = (blockIdx.x * blockDim.x + threadIdx.x) >> 5;
    int lane = threadIdx.x & 31;
    if (warp >= BT_) return;
    const float* hr = h1 + (size_t)warp * 256;
    float a0 = 0.f, a1 = 0.f, a2 = 0.f, a3 = 0.f;
    for (int k = lane; k < 256; k += 32) {
        float hv = __ldg(&hr[k]);
        a0 = fmaf(hv, __ldg(&Wn2[k]),       a0);
        a1 = fmaf(hv, __ldg(&Wn2[256 + k]), a1);
        a2 = fmaf(hv, __ldg(&Wn2[512 + k]), a2);
        a3 = fmaf(hv, __ldg(&Wn2[768 + k]), a3);
    }
#pragma unroll
    for (int o = 16; o > 0; o >>= 1) {
        a0 += __shfl_xor_sync(0xffffffff, a0, o);
        a1 += __shfl_xor_sync(0xffffffff, a1, o);
        a2 += __shfl_xor_sync(0xffffffff, a2, o);
        a3 += __shfl_xor_sync(0xffffffff, a3, o);
    }
    if (lane == 0) {
        mod[(size_t)warp * 4 + 0] = 0.5f + sigmoidf_(a0 + bn2[0]);
        mod[(size_t)warp * 4 + 1] = 0.5f + sigmoidf_(a1 + bn2[1]);
        mod[(size_t)warp * 4 + 2] = 0.5f + sigmoidf_(a2 + bn2[2]);
        mod[(size_t)warp * 4 + 3] = 0.5f + sigmoidf_(a3 + bn2[3]);
    }
}

// ---------------- in-place LayerNorm over E per row --------------------------
__global__ void ln_kernel(float* __restrict__ out,
                          const float* __restrict__ gamma,
                          const float* __restrict__ beta) {
    int row = blockIdx.x;
    float* p = out + (size_t)row * E_;
    int tid = threadIdx.x;          // 256
    float v[4];
    float s = 0.f, ss = 0.f;
#pragma unroll
    for (int i = 0; i < 4; i++) {
        v[i] = p[tid + i * 256];
        s += v[i];
        ss += v[i] * v[i];
    }
#pragma unroll
    for (int o = 16; o > 0; o >>= 1) {
        s  += __shfl_down_sync(0xffffffff, s,  o);
        ss += __shfl_down_sync(0xffffffff, ss, o);
    }
    __shared__ float shs[8], shss[8];
    __shared__ float mu_s, inv_s;
    int wid = tid >> 5, lane = tid & 31;
    if (lane == 0) { shs[wid] = s; shss[wid] = ss; }
    __syncthreads();
    if (tid == 0) {
        float S = 0.f, SS = 0.f;
#pragma unroll
        for (int w = 0; w < 8; w++) { S += shs[w]; SS += shss[w]; }
        float mu  = S / (float)E_;
        float var = SS / (float)E_ - mu * mu;
        mu_s = mu;
        inv_s = rsqrtf(var + 1e-5f);
    }
    __syncthreads();
    float mu = mu_s, iv = inv_s;
#pragma unroll
    for (int i = 0; i < 4; i++) {
        int c = tid + i * 256;
        p[c] = (v[i] - mu) * iv * __ldg(&gamma[c]) + __ldg(&beta[c]);
    }
}

// ---------------- launch -----------------------------------------------------
extern "C" void kernel_launch(void* const* d_in, const int* in_sizes, int n_in,
                              void* d_out, int out_size) {
    const float* x        = (const float*)d_in[0];
    const float* tau_ctx  = (const float*)d_in[1];
    const float* tau_raws = (const float*)d_in[2];
    const float* Wg       = (const float*)d_in[3];
    const float* bg       = (const float*)d_in[4];
    const float* Wn1      = (const float*)d_in[5];
    const float* bn1      = (const float*)d_in[6];
    const float* Wn2      = (const float*)d_in[7];
    const float* bn2      = (const float*)d_in[8];
    const float* blend    = (const float*)d_in[9];
    const float* Wsoma    = (const float*)d_in[10];
    const float* bsoma    = (const float*)d_in[11];
    const float* Wtemp    = (const float*)d_in[12];
    const float* btemp    = (const float*)d_in[13];
    const float* Wout     = (const float*)d_in[14];
    const float* gamma    = (const float*)d_in[15];
    const float* beta     = (const float*)d_in[16];
    float* out = (float*)d_out;

    float *ctx, *gated, *temporal, *gate, *sg, *h1, *mod, *seg, *seg4;
    cudaGetSymbolAddress((void**)&ctx,      g_ctx);
    cudaGetSymbolAddress((void**)&gated,    g_gated);
    cudaGetSymbolAddress((void**)&temporal, g_temporal);
    cudaGetSymbolAddress((void**)&gate,     g_gate);
    cudaGetSymbolAddress((void**)&sg,       g_sg);
    cudaGetSymbolAddress((void**)&h1,       g_h1);
    cudaGetSymbolAddress((void**)&mod,      g_mod);
    cudaGetSymbolAddress((void**)&seg,      g_seg);
    cudaGetSymbolAddress((void**)&seg4,     g_seg4);

    cudaFuncSetAttribute(gemm_mma, cudaFuncAttributeMaxDynamicSharedMemorySize, DYN_SMEM);

    const int NSEG_T = B_ * E_ * SEG_;   // 65536

    // 1) ctx = EMA(x, tau_ctx)  — segmented 3-pass
    ema_ctx_p1<<<NSEG_T / 256, 256>>>(x, tau_ctx, seg);
    ema_ctx_p2<<<(B_ * E_) / 256, 256>>>(tau_ctx, seg);
    ema_ctx_p3<<<NSEG_T / 256, 256>>>(x, tau_ctx, seg, ctx);

    // 2) gated = x * sigmoid([x,ctx] @ Wg^T + bg)
    {
        dim3 grid(E_ / 128, BT_ / 128);
        gemm_mma<<<grid, 256, DYN_SMEM>>>(x, ctx, E_, Wg, bg, x, gated, E_, 2 * E_, 1);
    }

    // 3) h1 = gelu(x @ Wn1^T + bn1)
    {
        dim3 grid(256 / 128, BT_ / 128);
        gemm_mma<<<grid, 256, DYN_SMEM>>>(x, nullptr, E_, Wn1, bn1, nullptr, h1, 256, E_, 2);
    }

    // 4) mod = 0.5 + sigmoid(h1 @ Wn2^T + bn2)
    mod_kernel<<<(BT_ * 32) / 256, 256>>>(h1, Wn2, bn2, mod);

    // 5) temporal — segmented 3-pass over 4 chains + blend
    ema_tr_p1<<<NSEG_T / 256, 256>>>(gated, mod, tau_raws, seg4);
    ema_tr_p2<<<(B_ * E_) / 256, 256>>>(tau_raws, seg4);
    ema_tr_p3<<<NSEG_T / 256, 256>>>(gated, mod, tau_raws, blend, seg4, temporal);

    // 6) gate = sigmoid(temporal @ Wtemp^T + btemp)
    {
        dim3 grid(E_ / 128, BT_ / 128);
        gemm_mma<<<grid, 256, DYN_SMEM>>>(temporal, nullptr, E_, Wtemp, btemp, nullptr, gate, E_, E_, 3);
    }

    // 7) sg = gelu(x @ Wsoma^T + bsoma) * gate
    {
        dim3 grid(E_ / 128, BT_ / 128);
        gemm_mma<<<grid, 256, DYN_SMEM>>>(x, nullptr, E_, Wsoma, bsoma, gate, sg, E_, E_, 4);
    }

    // 8) out = sg @ Wout^T
    {
        dim3 grid(E_ / 128, BT_ / 128);
        gemm_mma<<<grid, 256, DYN_SMEM>>>(sg, nullptr, E_, Wout, nullptr, nullptr, out, E_, E_, 0);
    }

    // 9) LayerNorm in place
    ln_kernel<<<BT_, 256>>>(out, gamma, beta);
}